// round 15
// baseline (speedup 1.0000x reference)
#include <cuda_runtime.h>

#define N_NODES 50000
#define N_EDGES 800000
#define CAP     64            // per-node bucket capacity (P(deg>64) ~ 2e-18)

// ---------------- scratch (no allocation allowed) ----------------
__device__ float g_agg[N_NODES * 128];   // layer-1 aggregated x
__device__ float g_h  [N_NODES * 128];   // layer-1 hidden activations
__device__ float g_P2 [N_NODES * 128];   // [h@W2l^T | h@W2r^T]
__device__ int   g_cnt[N_NODES];         // per-node fill counts (= degree)
__device__ int   g_elist[N_NODES * CAP]; // bucketed src lists
__device__ float g_B1[256 * 128];        // [W1l;W1r]^T k-major (K=256), tf32
__device__ float g_B2[128 * 128];        // [W2l;W2r]^T k-major (K=128), tf32

// ---------------- tf32 helpers ----------------
__device__ __forceinline__ float tf32r(float x) {
    unsigned r;
    asm("cvt.rna.tf32.f32 %0, %1;" : "=r"(r) : "f"(x));
    return __uint_as_float(r);
}
__device__ __forceinline__ unsigned tf32b(float x) {
    unsigned r;
    asm("cvt.rna.tf32.f32 %0, %1;" : "=r"(r) : "f"(x));
    return r;
}
__device__ __forceinline__ void cp16(unsigned smem_addr, const void* gptr) {
    asm volatile("cp.async.cg.shared.global [%0], [%1], 16;"
                 :: "r"(smem_addr), "l"(gptr));
}

// ---------------- weight prep: concatenated k-major B (tf32) --------------
__global__ void prep_weights(const float* __restrict__ W1l, const float* __restrict__ W1r,
                             const float* __restrict__ W2l, const float* __restrict__ W2r) {
    int t = blockIdx.x * blockDim.x + threadIdx.x;
    if (t < 256 * 128) {
        int k = t >> 7, o = t & 127;
        float v = (k < 128) ? W1l[o * 128 + k] : W1r[o * 128 + (k - 128)];
        g_B1[t] = tf32r(v);
    }
    int t2 = t - 256 * 128;
    if (t2 >= 0 && t2 < 128 * 128) {
        int k = t2 >> 7, o = t2 & 127;
        float v = (o < 64) ? W2l[o * 128 + k] : W2r[(o - 64) * 128 + k];
        g_B2[t2] = tf32r(v);
    }
}

// ---------------- single-pass bucketed CSR fill ----------------
__global__ void fill_buckets(const int* __restrict__ ei) {
    int e = blockIdx.x * blockDim.x + threadIdx.x;
    if (e < N_EDGES) {
        int dst = __ldg(&ei[N_EDGES + e]);
        int p = atomicAdd(&g_cnt[dst], 1);
        if (p < CAP) g_elist[dst * CAP + p] = __ldg(&ei[e]);
    }
}

// ---------------- layer-1 aggregation: warp per node, 128-wide ------------
__global__ void aggregate(const float* __restrict__ x_ext) {
    int t = blockIdx.x * blockDim.x + threadIdx.x;
    int w = t >> 5;
    int lane = t & 31;
    if (w >= N_NODES) return;
    int off = w * CAP;
    int d = g_cnt[w];
    int dr = min(d, CAP);
    float4 s = make_float4(0.f, 0.f, 0.f, 0.f);
#pragma unroll 4
    for (int i = 0; i < dr; i++) {
        int src = __ldg(&g_elist[off + i]);
        float4 v = *(const float4*)(x_ext + (size_t)src * 128 + lane * 4);
        s.x += v.x; s.y += v.y; s.z += v.z; s.w += v.w;
    }
    float inv = (d > 0) ? (1.f / (float)d) : 0.f;
    s.x *= inv; s.y *= inv; s.z *= inv; s.w *= inv;
    *(float4*)(g_agg + (size_t)w * 128 + lane * 4) = s;
}

// ------ layer-2 fused aggregate: out = agg(P2[:, :64])/deg + P2[w,64:]+b --
__global__ void aggregate_out(const float* __restrict__ bias,
                              float* __restrict__ outp) {
    int t = blockIdx.x * blockDim.x + threadIdx.x;
    int w = t >> 5;
    int lane = t & 31;
    if (w >= N_NODES) return;
    int off = w * CAP;
    int d = g_cnt[w];
    int dr = min(d, CAP);
    int half = lane >> 4;             // 0 or 1
    int sub  = lane & 15;
    const float* basep = g_P2 + sub * 4;
    float4 s = make_float4(0.f, 0.f, 0.f, 0.f);
    int i = 0;
#pragma unroll 2
    for (; i + 2 <= dr; i += 2) {
        int src = __ldg(&g_elist[off + i + half]);
        float4 v = *(const float4*)(basep + (size_t)src * 128);
        s.x += v.x; s.y += v.y; s.z += v.z; s.w += v.w;
    }
    if (i < dr && half == 0) {        // odd tail
        int src = __ldg(&g_elist[off + i]);
        float4 v = *(const float4*)(basep + (size_t)src * 128);
        s.x += v.x; s.y += v.y; s.z += v.z; s.w += v.w;
    }
    s.x += __shfl_xor_sync(0xffffffffu, s.x, 16);
    s.y += __shfl_xor_sync(0xffffffffu, s.y, 16);
    s.z += __shfl_xor_sync(0xffffffffu, s.z, 16);
    s.w += __shfl_xor_sync(0xffffffffu, s.w, 16);
    if (half == 0) {
        float inv = (d > 0) ? (1.f / (float)d) : 0.f;
        float4 r = *(const float4*)(g_P2 + (size_t)w * 128 + 64 + sub * 4);
        float4 b = *(const float4*)(bias + sub * 4);
        float4 o;
        o.x = s.x * inv + r.x + b.x;
        o.y = s.y * inv + r.y + b.y;
        o.z = s.z * inv + r.z + b.z;
        o.w = s.w * inv + r.w + b.w;
        *(float4*)(outp + (size_t)w * 64 + sub * 4) = o;
    }
}

// ---------------- TF32 mma GEMM, cp.async double-buffered -----------------
// LAYER==1: C = [agg | x] @ B1 (K=256), epilogue bias+relu -> g_h
// LAYER==2: C = h @ B2 (K=128), plain store -> g_P2
// A staged raw fp32 (tf32 cvt in fragment load); B pre-rounded at prep.
template <int LAYER>
__global__ void __launch_bounds__(256, 2)
gemm_mma(const float* __restrict__ A2ext, const float* __restrict__ bias) {
    constexpr int KTOT = (LAYER == 1) ? 256 : 128;
    constexpr int NTILE = KTOT / 32;
    constexpr int BN  = 128;
    constexpr int WN  = 4;
    constexpr int WMT = 64;
    constexpr int WNT = 32;
    constexpr int MT  = 4;
    constexpr int NT  = 4;
    constexpr int BM = 128;
    constexpr int BK = 32;
    constexpr int ASTRIDE = BK + 4;               // 36
    constexpr int BSTRIDE = BN + 4;               // 132
    constexpr int ASZ = BM * ASTRIDE;             // 4608 floats
    constexpr int BSZ = BK * BSTRIDE;             // 4224 floats

    const float* B = (LAYER == 1) ? g_B1 : g_B2;
    float*       C = (LAYER == 1) ? g_h  : g_P2;

    extern __shared__ float sm[];
    float* Asb[2] = { sm, sm + ASZ };
    float* Bsb[2] = { sm + 2 * ASZ, sm + 2 * ASZ + BSZ };

    int t    = threadIdx.x;
    int wid  = t >> 5;
    int lane = t & 31;
    int lr   = lane >> 2;                 // 0..7
    int lc   = lane & 3;                  // 0..3
    int warp_m = wid / WN;
    int warp_n = wid % WN;
    int m0 = blockIdx.x * BM;

    // tile loader: issue cp.async (or zero-store for OOB rows) into buffer b
    auto load_tile = [&](int tile, int b) {
        int kc = tile * BK;
        const float* Asrc = (LAYER == 2) ? (const float*)g_h
                           : ((kc < 128) ? g_agg : A2ext);
        int kbase = (LAYER == 2) ? kc : ((kc < 128) ? kc : (kc - 128));
#pragma unroll
        for (int q = 0; q < 4; q++) {
            int idx  = t + q * 256;           // 0..1023
            int row  = idx >> 3;
            int c4   = (idx & 7) * 4;
            int node = m0 + row;
            float* dst = &Asb[b][row * ASTRIDE + c4];
            if (node < N_NODES)
                cp16((unsigned)__cvta_generic_to_shared(dst),
                     Asrc + (size_t)node * 128 + kbase + c4);
            else
                *(float4*)dst = make_float4(0.f, 0.f, 0.f, 0.f);
        }
#pragma unroll
        for (int q = 0; q < 4; q++) {
            int idx  = t + q * 256;
            int kk   = idx >> 5;              // 32 float4 per k-row
            int col4 = idx & 31;
            cp16((unsigned)__cvta_generic_to_shared(&Bsb[b][kk * BSTRIDE + col4 * 4]),
                 B + (size_t)(kc + kk) * BN + col4 * 4);
        }
        asm volatile("cp.async.commit_group;");
    };

    float acc[MT][NT][4];
#pragma unroll
    for (int i = 0; i < MT; i++)
#pragma unroll
        for (int j = 0; j < NT; j++)
#pragma unroll
            for (int q = 0; q < 4; q++) acc[i][j][q] = 0.f;

    // prologue
    load_tile(0, 0);
    asm volatile("cp.async.wait_group 0;");
    __syncthreads();

    int buf = 0;
    for (int tile = 0; tile < NTILE; tile++) {
        if (tile + 1 < NTILE) load_tile(tile + 1, buf ^ 1);

        const float* As = Asb[buf];
        const float* Bs = Bsb[buf];
#pragma unroll
        for (int ks = 0; ks < 4; ks++) {
            int kk = ks * 8;
            unsigned a[MT][4];
#pragma unroll
            for (int mt = 0; mt < MT; mt++) {
                const float* ap = &As[(warp_m * WMT + mt * 16 + lr) * ASTRIDE + kk + lc];
                a[mt][0] = tf32b(ap[0]);
                a[mt][1] = tf32b(ap[8 * ASTRIDE]);
                a[mt][2] = tf32b(ap[4]);
                a[mt][3] = tf32b(ap[8 * ASTRIDE + 4]);
            }
            unsigned b[NT][2];
#pragma unroll
            for (int nt = 0; nt < NT; nt++) {
                const float* bp = &Bs[(kk + lc) * BSTRIDE + warp_n * WNT + nt * 8 + lr];
                b[nt][0] = __float_as_uint(bp[0]);
                b[nt][1] = __float_as_uint(bp[4 * BSTRIDE]);
            }
#pragma unroll
            for (int mt = 0; mt < MT; mt++)
#pragma unroll
                for (int nt = 0; nt < NT; nt++) {
                    asm("mma.sync.aligned.m16n8k8.row.col.f32.tf32.tf32.f32 "
                        "{%0,%1,%2,%3}, {%4,%5,%6,%7}, {%8,%9}, {%0,%1,%2,%3};"
                        : "+f"(acc[mt][nt][0]), "+f"(acc[mt][nt][1]),
                          "+f"(acc[mt][nt][2]), "+f"(acc[mt][nt][3])
                        : "r"(a[mt][0]), "r"(a[mt][1]), "r"(a[mt][2]), "r"(a[mt][3]),
                          "r"(b[nt][0]), "r"(b[nt][1]));
                }
        }
        if (tile + 1 < NTILE)
            asm volatile("cp.async.wait_group 0;");
        __syncthreads();
        buf ^= 1;
    }

    // ---- epilogue ----
#pragma unroll
    for (int mt = 0; mt < MT; mt++) {
#pragma unroll
        for (int nt = 0; nt < NT; nt++) {
            int r = m0 + warp_m * WMT + mt * 16 + lr;
            int c = warp_n * WNT + nt * 8 + 2 * lc;
            float2 v0, v1;
            if (LAYER == 1) {
                float2 bv = *(const float2*)(bias + c);
                v0 = make_float2(fmaxf(acc[mt][nt][0] + bv.x, 0.f),
                                 fmaxf(acc[mt][nt][1] + bv.y, 0.f));
                v1 = make_float2(fmaxf(acc[mt][nt][2] + bv.x, 0.f),
                                 fmaxf(acc[mt][nt][3] + bv.y, 0.f));
            } else {
                v0 = make_float2(acc[mt][nt][0], acc[mt][nt][1]);
                v1 = make_float2(acc[mt][nt][2], acc[mt][nt][3]);
            }
            if (r < N_NODES)     *(float2*)(C + (size_t)r * BN + c)       = v0;
            if (r + 8 < N_NODES) *(float2*)(C + (size_t)(r + 8) * BN + c) = v1;
        }
    }
}

// ---------------- launcher ----------------
extern "C" void kernel_launch(void* const* d_in, const int* in_sizes, int n_in,
                              void* d_out, int out_size) {
    const float* x   = (const float*)d_in[0];
    const int*   ei  = (const int*)d_in[1];       // int32 (JAX x64 disabled)
    const float* W1l = (const float*)d_in[2];
    const float* b1l = (const float*)d_in[3];
    const float* W1r = (const float*)d_in[4];
    const float* W2l = (const float*)d_in[5];
    const float* b2l = (const float*)d_in[6];
    const float* W2r = (const float*)d_in[7];
    float* out = (float*)d_out;

    const int T = 256;
    int g_prep = (256 * 128 + 128 * 128 + T - 1) / T;
    int g_edge = (N_EDGES + T - 1) / T;
    int g_aggr = (N_NODES * 32 + T - 1) / T;
    int g_gemm = (N_NODES + 127) / 128;

    // dynamic smem: 2*(A + B) buffers
    const int SMEM_BYTES = 2 * (128 * 36 + 32 * 132) * 4;   // 70656
    static int attr_done = 0;
    if (!attr_done) {
        cudaFuncSetAttribute(gemm_mma<1>, cudaFuncAttributeMaxDynamicSharedMemorySize, SMEM_BYTES);
        cudaFuncSetAttribute(gemm_mma<2>, cudaFuncAttributeMaxDynamicSharedMemorySize, SMEM_BYTES);
        attr_done = 1;
    }

    void* cntp = nullptr;
    cudaGetSymbolAddress(&cntp, g_cnt);
    cudaMemsetAsync(cntp, 0, N_NODES * sizeof(int));

    fill_buckets<<<g_edge, T>>>(ei);
    prep_weights<<<g_prep, T>>>(W1l, W1r, W2l, W2r);
    aggregate<<<g_aggr, T>>>(x);
    gemm_mma<1><<<g_gemm, T, SMEM_BYTES>>>(x, b1l);
    gemm_mma<2><<<g_gemm, T, SMEM_BYTES>>>(nullptr, nullptr);
    aggregate_out<<<g_aggr, T>>>(b2l, out);
}

// round 16
// speedup vs baseline: 1.1678x; 1.1678x over previous
#include <cuda_runtime.h>

#define N_NODES 50000
#define N_EDGES 800000
#define CAP     64            // per-node bucket capacity (P(deg>64) ~ 2e-18)

// ---------------- scratch (no allocation allowed) ----------------
__device__ float g_agg[N_NODES * 128];   // layer-1 aggregated x
__device__ float g_P2 [N_NODES * 128];   // [h@W2l^T | h@W2r^T]
__device__ int   g_cnt[N_NODES];         // per-node fill counts (= degree)
__device__ int   g_elist[N_NODES * CAP]; // bucketed src lists
__device__ float g_B1[256 * 128];        // [W1l;W1r]^T k-major (K=256), tf32
__device__ float g_B2[128 * 128];        // [W2l;W2r]^T k-major (K=128), tf32

// ---------------- tf32 helper ----------------
__device__ __forceinline__ float tf32r(float x) {
    unsigned r;
    asm("cvt.rna.tf32.f32 %0, %1;" : "=r"(r) : "f"(x));
    return __uint_as_float(r);
}

// ---------------- weight prep: concatenated k-major B (tf32) --------------
__global__ void prep_weights(const float* __restrict__ W1l, const float* __restrict__ W1r,
                             const float* __restrict__ W2l, const float* __restrict__ W2r) {
    int t = blockIdx.x * blockDim.x + threadIdx.x;
    if (t < 256 * 128) {
        int k = t >> 7, o = t & 127;
        float v = (k < 128) ? W1l[o * 128 + k] : W1r[o * 128 + (k - 128)];
        g_B1[t] = tf32r(v);
    }
    int t2 = t - 256 * 128;
    if (t2 >= 0 && t2 < 128 * 128) {
        int k = t2 >> 7, o = t2 & 127;
        float v = (o < 64) ? W2l[o * 128 + k] : W2r[(o - 64) * 128 + k];
        g_B2[t2] = tf32r(v);
    }
}

// ---------------- single-pass bucketed CSR fill ----------------
__global__ void fill_buckets(const int* __restrict__ ei) {
    int e = blockIdx.x * blockDim.x + threadIdx.x;
    if (e < N_EDGES) {
        int dst = __ldg(&ei[N_EDGES + e]);
        int p = atomicAdd(&g_cnt[dst], 1);
        if (p < CAP) g_elist[dst * CAP + p] = __ldg(&ei[e]);
    }
}

// ---------------- layer-1 aggregation: warp per node, 128-wide ------------
__global__ void aggregate(const float* __restrict__ x_ext) {
    int t = blockIdx.x * blockDim.x + threadIdx.x;
    int w = t >> 5;
    int lane = t & 31;
    if (w >= N_NODES) return;
    int off = w * CAP;
    int d = g_cnt[w];
    int dr = min(d, CAP);
    float4 s = make_float4(0.f, 0.f, 0.f, 0.f);
#pragma unroll 4
    for (int i = 0; i < dr; i++) {
        int src = __ldg(&g_elist[off + i]);
        float4 v = *(const float4*)(x_ext + (size_t)src * 128 + lane * 4);
        s.x += v.x; s.y += v.y; s.z += v.z; s.w += v.w;
    }
    float inv = (d > 0) ? (1.f / (float)d) : 0.f;
    s.x *= inv; s.y *= inv; s.z *= inv; s.w *= inv;
    *(float4*)(g_agg + (size_t)w * 128 + lane * 4) = s;
}

// ------ layer-2 fused aggregate: out = agg(P2[:, :64])/deg + P2[w,64:]+b --
__global__ void aggregate_out(const float* __restrict__ bias,
                              float* __restrict__ outp) {
    int t = blockIdx.x * blockDim.x + threadIdx.x;
    int w = t >> 5;
    int lane = t & 31;
    if (w >= N_NODES) return;
    int off = w * CAP;
    int d = g_cnt[w];
    int dr = min(d, CAP);
    int half = lane >> 4;             // 0 or 1
    int sub  = lane & 15;
    const float* basep = g_P2 + sub * 4;
    float4 s = make_float4(0.f, 0.f, 0.f, 0.f);
    int i = 0;
#pragma unroll 2
    for (; i + 2 <= dr; i += 2) {
        int src = __ldg(&g_elist[off + i + half]);
        float4 v = *(const float4*)(basep + (size_t)src * 128);
        s.x += v.x; s.y += v.y; s.z += v.z; s.w += v.w;
    }
    if (i < dr && half == 0) {        // odd tail
        int src = __ldg(&g_elist[off + i]);
        float4 v = *(const float4*)(basep + (size_t)src * 128);
        s.x += v.x; s.y += v.y; s.z += v.z; s.w += v.w;
    }
    s.x += __shfl_xor_sync(0xffffffffu, s.x, 16);
    s.y += __shfl_xor_sync(0xffffffffu, s.y, 16);
    s.z += __shfl_xor_sync(0xffffffffu, s.z, 16);
    s.w += __shfl_xor_sync(0xffffffffu, s.w, 16);
    if (half == 0) {
        float inv = (d > 0) ? (1.f / (float)d) : 0.f;
        float4 r = *(const float4*)(g_P2 + (size_t)w * 128 + 64 + sub * 4);
        float4 b = *(const float4*)(bias + sub * 4);
        float4 o;
        o.x = s.x * inv + r.x + b.x;
        o.y = s.y * inv + r.y + b.y;
        o.z = s.z * inv + r.z + b.z;
        o.w = s.w * inv + r.w + b.w;
        *(float4*)(outp + (size_t)w * 64 + sub * 4) = o;
    }
}

// ---------------- FUSED double GEMM (tf32 m16n8k8) ------------------------
// Phase 1: acc = [agg | x] @ B1 (K=256);  h = relu(acc + b1) -> SMEM (tf32)
// Phase 2: P2  = h_smem @ B2   (K=128) -> global.  h never hits DRAM.
// SMEM: H = 4 chunks of [128 rows][32 k] stride 36 (phase-1 staging aliases
// chunk 0); Bs = [32][128] stride 132.
__global__ void __launch_bounds__(256, 2)
gemm_fused(const float* __restrict__ x_ext, const float* __restrict__ bias) {
    constexpr int BN  = 128;
    constexpr int WN  = 4;
    constexpr int WMT = 64;
    constexpr int WNT = 32;
    constexpr int MT  = 4;
    constexpr int NT  = 4;
    constexpr int BM = 128;
    constexpr int BK = 32;
    constexpr int ASTRIDE = BK + 4;               // 36
    constexpr int BSTRIDE = BN + 4;               // 132
    constexpr int CHUNK = BM * ASTRIDE;           // 4608 floats per k-chunk

    extern __shared__ float sm[];
    float* H  = sm;                               // 4 * CHUNK
    float* Bs = sm + 4 * CHUNK;                   // BK * BSTRIDE
    float* As = H;                                // phase-1 staging (chunk 0)

    int t    = threadIdx.x;
    int wid  = t >> 5;
    int lane = t & 31;
    int lr   = lane >> 2;                 // 0..7
    int lc   = lane & 3;                  // 0..3
    int warp_m = wid / WN;
    int warp_n = wid % WN;
    int m0 = blockIdx.x * BM;

    float acc[MT][NT][4];
#pragma unroll
    for (int i = 0; i < MT; i++)
#pragma unroll
        for (int j = 0; j < NT; j++)
#pragma unroll
            for (int q = 0; q < 4; q++) acc[i][j][q] = 0.f;

    // ================= phase 1: K=256 over B1 =================
    for (int kc = 0; kc < 256; kc += BK) {
        const float* Asrc = (kc < 128) ? g_agg : x_ext;
        int kbase = (kc < 128) ? kc : (kc - 128);
#pragma unroll
        for (int q = 0; q < 4; q++) {
            int idx  = t + q * 256;           // 0..1023
            int row  = idx >> 3;
            int c4   = (idx & 7) * 4;
            int node = m0 + row;
            float4 v = make_float4(0.f, 0.f, 0.f, 0.f);
            if (node < N_NODES)
                v = *(const float4*)(Asrc + (size_t)node * 128 + kbase + c4);
            float* dst = &As[row * ASTRIDE + c4];
            dst[0] = tf32r(v.x); dst[1] = tf32r(v.y);
            dst[2] = tf32r(v.z); dst[3] = tf32r(v.w);
        }
#pragma unroll
        for (int q = 0; q < 4; q++) {
            int idx  = t + q * 256;
            int kk   = idx >> 5;              // 32 float4 per k-row
            int col4 = idx & 31;
            *(float4*)&Bs[kk * BSTRIDE + col4 * 4] =
                *(const float4*)(g_B1 + (size_t)(kc + kk) * BN + col4 * 4);
        }
        __syncthreads();
#pragma unroll
        for (int ks = 0; ks < 4; ks++) {
            int kk = ks * 8;
            unsigned a[MT][4];
#pragma unroll
            for (int mt = 0; mt < MT; mt++) {
                const float* ap = &As[(warp_m * WMT + mt * 16 + lr) * ASTRIDE + kk + lc];
                a[mt][0] = __float_as_uint(ap[0]);
                a[mt][1] = __float_as_uint(ap[8 * ASTRIDE]);
                a[mt][2] = __float_as_uint(ap[4]);
                a[mt][3] = __float_as_uint(ap[8 * ASTRIDE + 4]);
            }
            unsigned b[NT][2];
#pragma unroll
            for (int nt = 0; nt < NT; nt++) {
                const float* bp = &Bs[(kk + lc) * BSTRIDE + warp_n * WNT + nt * 8 + lr];
                b[nt][0] = __float_as_uint(bp[0]);
                b[nt][1] = __float_as_uint(bp[4 * BSTRIDE]);
            }
#pragma unroll
            for (int mt = 0; mt < MT; mt++)
#pragma unroll
                for (int nt = 0; nt < NT; nt++) {
                    asm("mma.sync.aligned.m16n8k8.row.col.f32.tf32.tf32.f32 "
                        "{%0,%1,%2,%3}, {%4,%5,%6,%7}, {%8,%9}, {%0,%1,%2,%3};"
                        : "+f"(acc[mt][nt][0]), "+f"(acc[mt][nt][1]),
                          "+f"(acc[mt][nt][2]), "+f"(acc[mt][nt][3])
                        : "r"(a[mt][0]), "r"(a[mt][1]), "r"(a[mt][2]), "r"(a[mt][3]),
                          "r"(b[nt][0]), "r"(b[nt][1]));
                }
        }
        __syncthreads();
    }

    // ---- epilogue 1: h = relu(acc + b1) -> SMEM (tf32-rounded), zero acc --
#pragma unroll
    for (int mt = 0; mt < MT; mt++) {
#pragma unroll
        for (int nt = 0; nt < NT; nt++) {
            int rl = warp_m * WMT + mt * 16 + lr;          // local row
            int c  = warp_n * WNT + nt * 8 + 2 * lc;       // h column (= k)
            float2 bv = *(const float2*)(bias + c);
            int ch = c >> 5;
            int cw = c & 31;
            float* h0 = &H[ch * CHUNK + rl * ASTRIDE + cw];
            h0[0] = tf32r(fmaxf(acc[mt][nt][0] + bv.x, 0.f));
            h0[1] = tf32r(fmaxf(acc[mt][nt][1] + bv.y, 0.f));
            float* h1 = h0 + 8 * ASTRIDE;
            h1[0] = tf32r(fmaxf(acc[mt][nt][2] + bv.x, 0.f));
            h1[1] = tf32r(fmaxf(acc[mt][nt][3] + bv.y, 0.f));
#pragma unroll
            for (int q = 0; q < 4; q++) acc[mt][nt][q] = 0.f;
        }
    }
    __syncthreads();

    // ================= phase 2: K=128 over B2, A = h in SMEM ==============
    for (int tile = 0; tile < 4; tile++) {
#pragma unroll
        for (int q = 0; q < 4; q++) {
            int idx  = t + q * 256;
            int kk   = idx >> 5;
            int col4 = idx & 31;
            *(float4*)&Bs[kk * BSTRIDE + col4 * 4] =
                *(const float4*)(g_B2 + (size_t)(tile * BK + kk) * BN + col4 * 4);
        }
        __syncthreads();
        const float* As2 = H + tile * CHUNK;
#pragma unroll
        for (int ks = 0; ks < 4; ks++) {
            int kk = ks * 8;
            unsigned a[MT][4];
#pragma unroll
            for (int mt = 0; mt < MT; mt++) {
                const float* ap = &As2[(warp_m * WMT + mt * 16 + lr) * ASTRIDE + kk + lc];
                a[mt][0] = __float_as_uint(ap[0]);
                a[mt][1] = __float_as_uint(ap[8 * ASTRIDE]);
                a[mt][2] = __float_as_uint(ap[4]);
                a[mt][3] = __float_as_uint(ap[8 * ASTRIDE + 4]);
            }
            unsigned b[NT][2];
#pragma unroll
            for (int nt = 0; nt < NT; nt++) {
                const float* bp = &Bs[(kk + lc) * BSTRIDE + warp_n * WNT + nt * 8 + lr];
                b[nt][0] = __float_as_uint(bp[0]);
                b[nt][1] = __float_as_uint(bp[4 * BSTRIDE]);
            }
#pragma unroll
            for (int mt = 0; mt < MT; mt++)
#pragma unroll
                for (int nt = 0; nt < NT; nt++) {
                    asm("mma.sync.aligned.m16n8k8.row.col.f32.tf32.tf32.f32 "
                        "{%0,%1,%2,%3}, {%4,%5,%6,%7}, {%8,%9}, {%0,%1,%2,%3};"
                        : "+f"(acc[mt][nt][0]), "+f"(acc[mt][nt][1]),
                          "+f"(acc[mt][nt][2]), "+f"(acc[mt][nt][3])
                        : "r"(a[mt][0]), "r"(a[mt][1]), "r"(a[mt][2]), "r"(a[mt][3]),
                          "r"(b[nt][0]), "r"(b[nt][1]));
                }
        }
        __syncthreads();
    }

    // ---- epilogue 2: store P2 ----
#pragma unroll
    for (int mt = 0; mt < MT; mt++) {
#pragma unroll
        for (int nt = 0; nt < NT; nt++) {
            int r = m0 + warp_m * WMT + mt * 16 + lr;
            int c = warp_n * WNT + nt * 8 + 2 * lc;
            if (r < N_NODES)
                *(float2*)(g_P2 + (size_t)r * BN + c) =
                    make_float2(acc[mt][nt][0], acc[mt][nt][1]);
            if (r + 8 < N_NODES)
                *(float2*)(g_P2 + (size_t)(r + 8) * BN + c) =
                    make_float2(acc[mt][nt][2], acc[mt][nt][3]);
        }
    }
}

// ---------------- launcher ----------------
extern "C" void kernel_launch(void* const* d_in, const int* in_sizes, int n_in,
                              void* d_out, int out_size) {
    const float* x   = (const float*)d_in[0];
    const int*   ei  = (const int*)d_in[1];       // int32 (JAX x64 disabled)
    const float* W1l = (const float*)d_in[2];
    const float* b1l = (const float*)d_in[3];
    const float* W1r = (const float*)d_in[4];
    const float* W2l = (const float*)d_in[5];
    const float* b2l = (const float*)d_in[6];
    const float* W2r = (const float*)d_in[7];
    float* out = (float*)d_out;

    const int T = 256;
    int g_prep = (256 * 128 + 128 * 128 + T - 1) / T;
    int g_edge = (N_EDGES + T - 1) / T;
    int g_aggr = (N_NODES * 32 + T - 1) / T;
    int g_gemm = (N_NODES + 127) / 128;

    // smem: H (4*4608) + Bs (32*132) floats
    const int SMEM_BYTES = (4 * 128 * 36 + 32 * 132) * 4;   // 90624
    static int attr_done = 0;
    if (!attr_done) {
        cudaFuncSetAttribute(gemm_fused, cudaFuncAttributeMaxDynamicSharedMemorySize, SMEM_BYTES);
        attr_done = 1;
    }

    void* cntp = nullptr;
    cudaGetSymbolAddress(&cntp, g_cnt);
    cudaMemsetAsync(cntp, 0, N_NODES * sizeof(int));

    fill_buckets<<<g_edge, T>>>(ei);                   // kernel 1
    prep_weights<<<g_prep, T>>>(W1l, W1r, W2l, W2r);   // kernel 2
    aggregate<<<g_aggr, T>>>(x);                       // kernel 3
    gemm_fused<<<g_gemm, T, SMEM_BYTES>>>(x, b1l);     // kernel 4 (ncu-captured)
    aggregate_out<<<g_aggr, T>>>(b2l, out);            // kernel 5
}